// round 2
// baseline (speedup 1.0000x reference)
#include <cuda_runtime.h>
#include <math.h>

#define BB   256      // batch
#define EMB  512
#define CLS  20000

#define BM 128
#define BN 128
#define BK 8

// ---------------- device scratch (no allocations allowed) ----------------
__device__ float g_inv_norm[CLS];
__device__ float g_xlen[BB];
__device__ float g_Wy[BB * EMB];      // gathered normalized target columns
__device__ float g_inter_sum;
__device__ float g_row_ce[BB];
__device__ int   g_row_correct[BB];

// ---------------- init ----------------
__global__ void k_init() {
    if (threadIdx.x == 0) g_inter_sum = 0.0f;
}

// ---------------- column inverse norms of W ----------------
__global__ void k_colnorm(const float* __restrict__ W) {
    int j = blockIdx.x * blockDim.x + threadIdx.x;
    if (j >= CLS) return;
    float s = 0.0f;
#pragma unroll 8
    for (int i = 0; i < EMB; i++) {
        float v = W[i * CLS + j];
        s += v * v;
    }
    g_inv_norm[j] = 1.0f / sqrtf(s);
}

// ---------------- per-row xlen + gather Wy ----------------
__global__ void k_prep(const float* __restrict__ emb,
                       const float* __restrict__ W,
                       const int* __restrict__ y) {
    int b = blockIdx.x;
    int tid = threadIdx.x;   // 128 threads
    float s = 0.0f;
    for (int k = tid; k < EMB; k += 128) {
        float v = emb[b * EMB + k];
        s += v * v;
    }
    __shared__ float sm[128];
    sm[tid] = s;
    __syncthreads();
    for (int o = 64; o > 0; o >>= 1) {
        if (tid < o) sm[tid] += sm[tid + o];
        __syncthreads();
    }
    if (tid == 0) g_xlen[b] = sqrtf(sm[0]);

    int t = y[b];
    float invn = g_inv_norm[t];
    for (int k = tid; k < EMB; k += 128)
        g_Wy[b * EMB + k] = W[k * CLS + t] * invn;
}

// ---------------- fused GEMM: [emb; Wy] (512x512) @ W (512x20000) ----------------
// rows 0..255  -> cos_s written to logits
// rows 256..511-> inter accumulation
__global__ __launch_bounds__(256) void k_gemm(const float* __restrict__ emb,
                                              const float* __restrict__ W,
                                              const int* __restrict__ y,
                                              float* __restrict__ logits) {
    __shared__ float As[BK][BM];
    __shared__ float Bs[BK][BN];

    int tid = threadIdx.x;
    int bn = blockIdx.x, bm = blockIdx.y;
    int rowBase = bm * BM;
    int colBase = bn * BN;

    // A loader: 128 rows x 8 k, 4 consecutive k per thread
    int aRow = tid >> 1;
    int aK   = (tid & 1) * 4;
    int gRow = rowBase + aRow;
    // B loader: 8 k-rows x 128 cols, 4 consecutive cols per thread
    int bRow = tid >> 5;
    int bCol = (tid & 31) * 4;
    int gCol = colBase + bCol;

    float acc[8][8];
#pragma unroll
    for (int i = 0; i < 8; i++)
#pragma unroll
        for (int j = 0; j < 8; j++) acc[i][j] = 0.0f;

    int ty = tid >> 4, tx = tid & 15;

    for (int kt = 0; kt < EMB; kt += BK) {
        float4 av;
        if (gRow < BB)
            av = *(const float4*)&emb[gRow * EMB + kt + aK];
        else
            av = *(const float4*)&g_Wy[(gRow - BB) * EMB + kt + aK];
        As[aK + 0][aRow] = av.x;
        As[aK + 1][aRow] = av.y;
        As[aK + 2][aRow] = av.z;
        As[aK + 3][aRow] = av.w;

        float4 bv = make_float4(0.f, 0.f, 0.f, 0.f);
        if (gCol < CLS)  // CLS % 4 == 0, so full float4 is in-bounds
            bv = *(const float4*)&W[(kt + bRow) * CLS + gCol];
        *(float4*)&Bs[bRow][bCol] = bv;

        __syncthreads();

#pragma unroll
        for (int k = 0; k < BK; k++) {
            float ra[8], rb[8];
            *(float4*)&ra[0] = *(const float4*)&As[k][ty * 8];
            *(float4*)&ra[4] = *(const float4*)&As[k][ty * 8 + 4];
            *(float4*)&rb[0] = *(const float4*)&Bs[k][tx * 8];
            *(float4*)&rb[4] = *(const float4*)&Bs[k][tx * 8 + 4];
#pragma unroll
            for (int i = 0; i < 8; i++)
#pragma unroll
                for (int j = 0; j < 8; j++)
                    acc[i][j] += ra[i] * rb[j];
        }
        __syncthreads();
    }

    // epilogue
    float interLocal = 0.0f;
    int j0 = colBase + tx * 8;
#pragma unroll
    for (int i = 0; i < 8; i++) {
        int gm = rowBase + ty * 8 + i;
        if (gm < BB) {
            // cos_s path
            int b = gm;
            float xl = g_xlen[b];
            float inv_xl = 1.0f / xl;
            if (j0 < CLS) {  // CLS % 8 == 0 -> whole 8 valid
                // NOTE: logits base (d_out+1) is only 4-byte aligned -> scalar stores only.
#pragma unroll
                for (int jj = 0; jj < 8; jj++) {
                    float s = acc[i][jj] * g_inv_norm[j0 + jj];
                    float c = fminf(fmaxf(s * inv_xl, -1.0f), 1.0f);
                    logits[b * CLS + j0 + jj] = c * xl;
                }
            }
        } else {
            // inter path
            int b = gm - BB;
            int t = y[b];
            if (j0 < CLS) {
#pragma unroll
                for (int jj = 0; jj < 8; jj++) {
                    int j = j0 + jj;
                    if (j != t) {
                        float c2 = acc[i][jj] * g_inv_norm[j];
                        float d2 = fmaxf(2.0f - 2.0f * c2, 0.0f);
                        interLocal += 1.0f / d2;
                    }
                }
            }
        }
    }
    // warp reduce + atomic
#pragma unroll
    for (int o = 16; o > 0; o >>= 1)
        interLocal += __shfl_down_sync(0xffffffffu, interLocal, o);
    if ((tid & 31) == 0 && interLocal != 0.0f)
        atomicAdd(&g_inter_sum, interLocal);
}

// ---------------- per-row: margin target, log-softmax, argmax ----------------
__global__ __launch_bounds__(256) void k_rows(const float* __restrict__ logits,
                                              const int* __restrict__ y) {
    int b = blockIdx.x;
    int tid = threadIdx.x;
    int tgt = y[b];
    float xl = g_xlen[b];
    const float* row = logits + b * CLS;

    // margin-adjusted target value
    float cs_t = row[tgt];
    float ct = cs_t / xl;                       // already clipped
    float c2 = ct * ct;
    float cosm = 8.0f * c2 * c2 - 8.0f * c2 + 1.0f;
    const float PI_F = 3.14159265f;
    float theta = acosf(ct);
    float kk = floorf(4.0f * theta / PI_F);
    float sign = 1.0f - 2.0f * fmodf(kk, 2.0f);
    float phi = sign * cosm - 2.0f * kk;
    const float LAMB = 1500.0f / 1.1f;
    const float FCO = 1.0f / (1.0f + LAMB);
    float out_t = cs_t + FCO * (phi * xl - cs_t);

    // pass 1: row max of "output", argmax of cos_s
    float mx = -3.0e38f;
    float bv = -3.0e38f;
    int bi = CLS;
    for (int j = tid; j < CLS; j += 256) {
        float v = row[j];
        float ov = (j == tgt) ? out_t : v;
        mx = fmaxf(mx, ov);
        if (v > bv) { bv = v; bi = j; }   // per-thread stride ascending -> first occurrence kept
    }
    __shared__ float smx[256];
    __shared__ float sbv[256];
    __shared__ int   sbi[256];
    smx[tid] = mx; sbv[tid] = bv; sbi[tid] = bi;
    __syncthreads();
    for (int o = 128; o > 0; o >>= 1) {
        if (tid < o) {
            smx[tid] = fmaxf(smx[tid], smx[tid + o]);
            float v2 = sbv[tid + o]; int i2 = sbi[tid + o];
            if (v2 > sbv[tid] || (v2 == sbv[tid] && i2 < sbi[tid])) {
                sbv[tid] = v2; sbi[tid] = i2;
            }
        }
        __syncthreads();
    }
    float rmx = smx[0];
    int amax = sbi[0];
    __syncthreads();

    // pass 2: sum of exp
    float se = 0.0f;
    for (int j = tid; j < CLS; j += 256) {
        float v = row[j];
        float ov = (j == tgt) ? out_t : v;
        se += expf(ov - rmx);
    }
    smx[tid] = se;
    __syncthreads();
    for (int o = 128; o > 0; o >>= 1) {
        if (tid < o) smx[tid] += smx[tid + o];
        __syncthreads();
    }
    if (tid == 0) {
        float lse = logf(smx[0]);
        g_row_ce[b] = -(out_t - rmx - lse);
        g_row_correct[b] = (amax == tgt) ? 1 : 0;
    }
}

// ---------------- finalize scalars ----------------
__global__ __launch_bounds__(256) void k_final(float* __restrict__ out) {
    __shared__ float s[256];
    __shared__ int   c[256];
    int tid = threadIdx.x;
    s[tid] = g_row_ce[tid];
    c[tid] = g_row_correct[tid];
    __syncthreads();
    for (int o = 128; o > 0; o >>= 1) {
        if (tid < o) { s[tid] += s[tid + o]; c[tid] += c[tid + o]; }
        __syncthreads();
    }
    if (tid == 0) {
        float ce = s[0] / (float)BB;
        float inter = g_inter_sum / ((float)BB * (float)(CLS - 1));
        out[0] = ce + 0.01f * inter;                  // loss
        out[1 + BB * CLS] = (float)c[0] / (float)BB;  // acc
        out[2 + BB * CLS] = inter;                    // inter
    }
}

// ---------------- launch ----------------
extern "C" void kernel_launch(void* const* d_in, const int* in_sizes, int n_in,
                              void* d_out, int out_size) {
    const float* emb = (const float*)d_in[0];
    const int*   y   = (const int*)d_in[1];
    const float* W   = (const float*)d_in[2];
    float* out = (float*)d_out;
    float* logits = out + 1;   // logits0 at offset 1

    k_init<<<1, 32>>>();
    k_colnorm<<<(CLS + 255) / 256, 256>>>(W);
    k_prep<<<BB, 128>>>(emb, W, y);
    dim3 grid((CLS + BN - 1) / BN, (2 * BB) / BM);  // 157 x 4
    k_gemm<<<grid, 256>>>(emb, W, y, logits);
    k_rows<<<BB, 256>>>(logits, y);
    k_final<<<1, 256>>>(out);
}

// round 5
// speedup vs baseline: 1.7896x; 1.7896x over previous
#include <cuda_runtime.h>
#include <cuda_bf16.h>
#include <math.h>
#include <stdint.h>

#define BB   256
#define EMB  512
#define CLS  20000

#define MT   128
#define NT   128
#define KC   32
#define NCH  (EMB / KC)       // 16 k-chunks
#define SBUF 32768            // bytes per pipeline buffer (Ahi|Alo|Bhi|Blo @ 8KB)

// ---------------- device scratch (no allocations allowed) ----------------
__device__ __align__(16) __nv_bfloat16 g_Bhi[EMB * CLS];   // normalized W, hi
__device__ __align__(16) __nv_bfloat16 g_Blo[EMB * CLS];   // normalized W, lo
__device__ __align__(16) __nv_bfloat16 g_Ahi[2 * BB * EMB];
__device__ __align__(16) __nv_bfloat16 g_Alo[2 * BB * EMB];
__device__ float g_xlen[BB];
__device__ float g_inter_sum;
__device__ float g_row_ce[BB];
__device__ int   g_row_correct[BB];

// ---------------- PTX helpers (sm_100 baseline ISA only) ----------------
__device__ __forceinline__ uint32_t s2u(const void* p) {
    return (uint32_t)__cvta_generic_to_shared(p);
}
__device__ __forceinline__ void cp_async16(uint32_t dst, const void* src, int szbytes) {
    asm volatile("cp.async.cg.shared.global [%0], [%1], 16, %2;"
                 :: "r"(dst), "l"(src), "r"(szbytes));
}
#define CP_COMMIT() asm volatile("cp.async.commit_group;" ::: "memory")
#define CP_WAIT(n)  asm volatile("cp.async.wait_group %0;" :: "n"(n) : "memory")

__device__ __forceinline__ void ldm_x4(uint32_t* r, uint32_t addr) {
    asm volatile("ldmatrix.sync.aligned.m8n8.x4.shared.b16 {%0,%1,%2,%3}, [%4];"
                 : "=r"(r[0]), "=r"(r[1]), "=r"(r[2]), "=r"(r[3]) : "r"(addr));
}
__device__ __forceinline__ void ldm_x4_t(uint32_t* r, uint32_t addr) {
    asm volatile("ldmatrix.sync.aligned.m8n8.x4.trans.shared.b16 {%0,%1,%2,%3}, [%4];"
                 : "=r"(r[0]), "=r"(r[1]), "=r"(r[2]), "=r"(r[3]) : "r"(addr));
}
__device__ __forceinline__ void mma16816(float* c, const uint32_t* a,
                                         uint32_t b0, uint32_t b1) {
    asm volatile("mma.sync.aligned.m16n8k16.row.col.f32.bf16.bf16.f32 "
                 "{%0,%1,%2,%3}, {%4,%5,%6,%7}, {%8,%9}, {%0,%1,%2,%3};"
                 : "+f"(c[0]), "+f"(c[1]), "+f"(c[2]), "+f"(c[3])
                 : "r"(a[0]), "r"(a[1]), "r"(a[2]), "r"(a[3]), "r"(b0), "r"(b1));
}

// ---------------- small kernels ----------------
__global__ void k_init() { if (threadIdx.x == 0) g_inter_sum = 0.0f; }

// per-column: norm, normalize, bf16 hi/lo split (W read twice; L2-resident 2nd pass)
__global__ void k_wsplit(const float* __restrict__ W) {
    int j = blockIdx.x * blockDim.x + threadIdx.x;
    if (j >= CLS) return;
    float s = 0.0f;
#pragma unroll 8
    for (int i = 0; i < EMB; i++) {
        float v = W[(size_t)i * CLS + j];
        s += v * v;
    }
    float invn = 1.0f / sqrtf(s);
#pragma unroll 4
    for (int i = 0; i < EMB; i++) {
        float v = W[(size_t)i * CLS + j] * invn;
        __nv_bfloat16 h = __float2bfloat16(v);
        g_Bhi[(size_t)i * CLS + j] = h;
        g_Blo[(size_t)i * CLS + j] = __float2bfloat16(v - __bfloat162float(h));
    }
}

// 512 blocks: b<BB: emb split + xlen; else gather normalized target column
__global__ void k_prep(const float* __restrict__ emb,
                       const int* __restrict__ y) {
    int b = blockIdx.x;
    int tid = threadIdx.x;   // 128
    if (b < BB) {
        float s = 0.0f;
        for (int k = tid; k < EMB; k += 128) {
            float v = emb[b * EMB + k];
            s += v * v;
            __nv_bfloat16 h = __float2bfloat16(v);
            g_Ahi[b * EMB + k] = h;
            g_Alo[b * EMB + k] = __float2bfloat16(v - __bfloat162float(h));
        }
        __shared__ float sm[128];
        sm[tid] = s;
        __syncthreads();
        for (int o = 64; o > 0; o >>= 1) {
            if (tid < o) sm[tid] += sm[tid + o];
            __syncthreads();
        }
        if (tid == 0) g_xlen[b] = sqrtf(sm[0]);
    } else {
        int t = y[b - BB];
        for (int k = tid; k < EMB; k += 128) {
            g_Ahi[b * EMB + k] = g_Bhi[(size_t)k * CLS + t];
            g_Alo[b * EMB + k] = g_Blo[(size_t)k * CLS + t];
        }
    }
}

// ---------------- bf16 mma.sync fused GEMM ----------------
// D[512, 20000] = [emb; Wy]_split @ nm_W_split  (output already cos_s / cosWW scale-free)
// bm<2: cos rows -> logits; bm>=2: inter accumulation.
__global__ __launch_bounds__(256, 1) void k_gemm(const int* __restrict__ y,
                                                 float* __restrict__ logits) {
    extern __shared__ __align__(16) char dsm[];
    uint32_t sb = s2u(dsm);

    int tid  = threadIdx.x;
    int wid  = tid >> 5, lane = tid & 31;
    int wm   = wid & 1;           // M half (64 rows)
    int wn   = wid >> 1;          // N quarter (32 cols)
    int bn   = blockIdx.x, bm = blockIdx.y;
    int rowBase = bm * MT, colBase = bn * NT;

    float acc[4][4][4];
#pragma unroll
    for (int mi = 0; mi < 4; mi++)
#pragma unroll
        for (int ni = 0; ni < 4; ni++)
#pragma unroll
            for (int k = 0; k < 4; k++) acc[mi][ni][k] = 0.0f;

    // ---- async tile loader: A 128x32 (64B rows, chunk^((r>>1)&3)); B 32x128 (256B rows, chunk^(r&7))
    auto load_tiles = [&](int kc, int buf) {
        uint32_t base = sb + buf * SBUF;
#pragma unroll
        for (int i = 0; i < 2; i++) {
            int id = tid + 256 * i;                 // 512 chunks / split
            int r = id >> 2, c8 = id & 3;
            uint32_t soff = (uint32_t)(r * 64 + ((c8 ^ ((r >> 1) & 3)) << 4));
            size_t go = (size_t)(rowBase + r) * EMB + kc + c8 * 8;
            cp_async16(base + soff,        g_Ahi + go, 16);
            cp_async16(base + 8192 + soff, g_Alo + go, 16);
        }
#pragma unroll
        for (int i = 0; i < 2; i++) {
            int id = tid + 256 * i;                 // 512 chunks / split
            int r = id >> 4, c16 = id & 15;
            uint32_t soff = (uint32_t)(r * 256 + ((c16 ^ (r & 7)) << 4));
            int col = colBase + c16 * 8;
            int ok = (col + 8 <= CLS) ? 16 : 0;     // zero-fill OOB chunk
            size_t go = (size_t)(kc + r) * CLS + (ok ? col : colBase);
            cp_async16(base + 16384 + soff, g_Bhi + go, ok);
            cp_async16(base + 24576 + soff, g_Blo + go, ok);
        }
    };

    load_tiles(0, 0);
    CP_COMMIT();

    int ln15 = lane & 15, half = lane >> 4;

    for (int ch = 0; ch < NCH; ch++) {
        if (ch + 1 < NCH) { load_tiles((ch + 1) * KC, (ch + 1) & 1); CP_COMMIT(); }
        if (ch + 1 < NCH) { CP_WAIT(1); } else { CP_WAIT(0); }
        __syncthreads();

        uint32_t base = sb + (ch & 1) * SBUF;
#pragma unroll
        for (int ks = 0; ks < 2; ks++) {
            uint32_t ah[4][4], al[4][4], bh[2][4], bl[2][4];
#pragma unroll
            for (int mi = 0; mi < 4; mi++) {
                int r = wm * 64 + mi * 16 + ln15;
                int c8 = ks * 2 + half;
                uint32_t off = (uint32_t)(r * 64 + ((c8 ^ ((r >> 1) & 3)) << 4));
                ldm_x4(ah[mi], base + off);
                ldm_x4(al[mi], base + 8192 + off);
            }
#pragma unroll
            for (int nb = 0; nb < 2; nb++) {
                int r = ks * 16 + ln15;
                int c16 = wn * 4 + nb * 2 + half;
                uint32_t off = (uint32_t)(r * 256 + ((c16 ^ (r & 7)) << 4));
                ldm_x4_t(bh[nb], base + 16384 + off);
                ldm_x4_t(bl[nb], base + 24576 + off);
            }
            // product-outer: 16 independent acc chains between dependent HMMAs
#pragma unroll
            for (int mi = 0; mi < 4; mi++)
#pragma unroll
                for (int ni = 0; ni < 4; ni++)
                    mma16816(acc[mi][ni], ah[mi],
                             bh[ni >> 1][(ni & 1) * 2], bh[ni >> 1][(ni & 1) * 2 + 1]);
#pragma unroll
            for (int mi = 0; mi < 4; mi++)
#pragma unroll
                for (int ni = 0; ni < 4; ni++)
                    mma16816(acc[mi][ni], al[mi],
                             bh[ni >> 1][(ni & 1) * 2], bh[ni >> 1][(ni & 1) * 2 + 1]);
#pragma unroll
            for (int mi = 0; mi < 4; mi++)
#pragma unroll
                for (int ni = 0; ni < 4; ni++)
                    mma16816(acc[mi][ni], ah[mi],
                             bl[ni >> 1][(ni & 1) * 2], bl[ni >> 1][(ni & 1) * 2 + 1]);
        }
        __syncthreads();
    }

    // ---------------- epilogue ----------------
    if (bm < 2) {
        // raw acc -> SMEM [128][129], then coalesced clip+store
        float* epi = (float*)dsm;
#pragma unroll
        for (int mi = 0; mi < 4; mi++)
#pragma unroll
            for (int ni = 0; ni < 4; ni++)
#pragma unroll
                for (int k = 0; k < 4; k++) {
                    int row = wm * 64 + mi * 16 + (k >> 1) * 8 + (lane >> 2);
                    int col = wn * 32 + ni * 8 + (lane & 3) * 2 + (k & 1);
                    epi[row * 129 + col] = acc[mi][ni][k];
                }
        __syncthreads();
        int r0 = tid >> 7, c0 = tid & 127;
        int j = colBase + c0;
        if (j < CLS) {
#pragma unroll 8
            for (int rr = 0; rr < 64; rr++) {
                int mm = rr * 2 + r0;
                int b = rowBase + mm;
                float xl = g_xlen[b];
                float v = epi[mm * 129 + c0];
                float cv = fminf(fmaxf(v / xl, -1.0f), 1.0f);
                logits[(size_t)b * CLS + j] = cv * xl;
            }
        }
    } else {
        float il = 0.0f;
#pragma unroll
        for (int mi = 0; mi < 4; mi++) {
#pragma unroll
            for (int k2 = 0; k2 < 2; k2++) {
                int row = wm * 64 + mi * 16 + k2 * 8 + (lane >> 2);
                int b = rowBase + row - BB;
                int t = y[b];
#pragma unroll
                for (int ni = 0; ni < 4; ni++)
#pragma unroll
                    for (int p = 0; p < 2; p++) {
                        int j = colBase + wn * 32 + ni * 8 + (lane & 3) * 2 + p;
                        if (j < CLS && j != t) {
                            float c = acc[mi][ni][k2 * 2 + p];
                            float d2 = fmaxf(2.0f - 2.0f * c, 0.0f);
                            il += 1.0f / d2;
                        }
                    }
            }
        }
#pragma unroll
        for (int o = 16; o > 0; o >>= 1)
            il += __shfl_down_sync(0xffffffffu, il, o);
        if (lane == 0) atomicAdd(&g_inter_sum, il);
    }
}

// ---------------- per-row: margin target, log-softmax, argmax ----------------
__global__ __launch_bounds__(256) void k_rows(const float* __restrict__ logits,
                                              const int* __restrict__ y) {
    int b = blockIdx.x;
    int tid = threadIdx.x;
    int tgt = y[b];
    float xl = g_xlen[b];
    const float* row = logits + (size_t)b * CLS;

    float cs_t = row[tgt];
    float ct = cs_t / xl;
    float c2 = ct * ct;
    float cosm = 8.0f * c2 * c2 - 8.0f * c2 + 1.0f;
    const float PI_F = 3.14159265f;
    float theta = acosf(ct);
    float kk = floorf(4.0f * theta / PI_F);
    float sign = 1.0f - 2.0f * fmodf(kk, 2.0f);
    float phi = sign * cosm - 2.0f * kk;
    const float LAMB = 1500.0f / 1.1f;
    const float FCO = 1.0f / (1.0f + LAMB);
    float out_t = cs_t + FCO * (phi * xl - cs_t);

    float mx = -3.0e38f, bv = -3.0e38f;
    int bi = CLS;
    for (int j = tid; j < CLS; j += 256) {
        float v = row[j];
        float ov = (j == tgt) ? out_t : v;
        mx = fmaxf(mx, ov);
        if (v > bv) { bv = v; bi = j; }
    }
    __shared__ float smx[256];
    __shared__ float sbv[256];
    __shared__ int   sbi[256];
    smx[tid] = mx; sbv[tid] = bv; sbi[tid] = bi;
    __syncthreads();
    for (int o = 128; o > 0; o >>= 1) {
        if (tid < o) {
            smx[tid] = fmaxf(smx[tid], smx[tid + o]);
            float v2 = sbv[tid + o]; int i2 = sbi[tid + o];
            if (v2 > sbv[tid] || (v2 == sbv[tid] && i2 < sbi[tid])) {
                sbv[tid] = v2; sbi[tid] = i2;
            }
        }
        __syncthreads();
    }
    float rmx = smx[0];
    int amax = sbi[0];
    __syncthreads();

    float se = 0.0f;
    for (int j = tid; j < CLS; j += 256) {
        float v = row[j];
        float ov = (j == tgt) ? out_t : v;
        se += expf(ov - rmx);
    }
    smx[tid] = se;
    __syncthreads();
    for (int o = 128; o > 0; o >>= 1) {
        if (tid < o) smx[tid] += smx[tid + o];
        __syncthreads();
    }
    if (tid == 0) {
        float lse = logf(smx[0]);
        g_row_ce[b] = -(out_t - rmx - lse);
        g_row_correct[b] = (amax == tgt) ? 1 : 0;
    }
}

__global__ __launch_bounds__(256) void k_final(float* __restrict__ out) {
    __shared__ float s[256];
    __shared__ int   c[256];
    int tid = threadIdx.x;
    s[tid] = g_row_ce[tid];
    c[tid] = g_row_correct[tid];
    __syncthreads();
    for (int o = 128; o > 0; o >>= 1) {
        if (tid < o) { s[tid] += s[tid + o]; c[tid] += c[tid + o]; }
        __syncthreads();
    }
    if (tid == 0) {
        float ce = s[0] / (float)BB;
        float inter = g_inter_sum / ((float)BB * (float)(CLS - 1));
        out[0] = ce + 0.01f * inter;
        out[1 + BB * CLS] = (float)c[0] / (float)BB;
        out[2 + BB * CLS] = inter;
    }
}

// ---------------- launch ----------------
extern "C" void kernel_launch(void* const* d_in, const int* in_sizes, int n_in,
                              void* d_out, int out_size) {
    const float* emb = (const float*)d_in[0];
    const int*   y   = (const int*)d_in[1];
    const float* W   = (const float*)d_in[2];
    float* out = (float*)d_out;
    float* logits = out + 1;

    const int DSM = 68 * 1024;   // 2x32KB pipeline buffers; 128x129 f32 epi tile fits too
    cudaFuncSetAttribute(k_gemm, cudaFuncAttributeMaxDynamicSharedMemorySize, DSM);

    k_init<<<1, 32>>>();
    k_wsplit<<<(CLS + 255) / 256, 256>>>(W);
    k_prep<<<2 * BB, 128>>>(emb, y);
    dim3 grid((CLS + NT - 1) / NT, (2 * BB) / MT);   // 157 x 4
    k_gemm<<<grid, 256, DSM>>>(y, logits);
    k_rows<<<BB, 256>>>(logits, y);
    k_final<<<1, 256>>>(out);
}

// round 6
// speedup vs baseline: 2.3997x; 1.3409x over previous
#include <cuda_runtime.h>
#include <cuda_bf16.h>
#include <math.h>
#include <stdint.h>

#define BB   256
#define EMB  512
#define CLS  20000

#define MT   128
#define NT   128
#define KC   32
#define NCH  (EMB / KC)       // 16 k-chunks
#define SBUF 32768            // bytes per pipeline buffer (Ahi|Alo|Bhi|Blo @ 8KB)

// ---------------- device scratch (no allocations allowed) ----------------
__device__ __align__(16) __nv_bfloat16 g_Bhi[EMB * CLS];   // normalized W, hi
__device__ __align__(16) __nv_bfloat16 g_Blo[EMB * CLS];   // normalized W, lo
__device__ __align__(16) __nv_bfloat16 g_Ahi[2 * BB * EMB];
__device__ __align__(16) __nv_bfloat16 g_Alo[2 * BB * EMB];
__device__ float g_norm2[CLS];
__device__ float g_xlen[BB];
__device__ float g_inter_sum;
__device__ float g_row_ce[BB];
__device__ int   g_row_correct[BB];

// ---------------- PTX helpers (sm_100 baseline ISA only) ----------------
__device__ __forceinline__ uint32_t s2u(const void* p) {
    return (uint32_t)__cvta_generic_to_shared(p);
}
__device__ __forceinline__ void cp_async16(uint32_t dst, const void* src, int szbytes) {
    asm volatile("cp.async.cg.shared.global [%0], [%1], 16, %2;"
                 :: "r"(dst), "l"(src), "r"(szbytes));
}
#define CP_COMMIT() asm volatile("cp.async.commit_group;" ::: "memory")
#define CP_WAIT(n)  asm volatile("cp.async.wait_group %0;" :: "n"(n) : "memory")

__device__ __forceinline__ void ldm_x4(uint32_t* r, uint32_t addr) {
    asm volatile("ldmatrix.sync.aligned.m8n8.x4.shared.b16 {%0,%1,%2,%3}, [%4];"
                 : "=r"(r[0]), "=r"(r[1]), "=r"(r[2]), "=r"(r[3]) : "r"(addr));
}
__device__ __forceinline__ void ldm_x4_t(uint32_t* r, uint32_t addr) {
    asm volatile("ldmatrix.sync.aligned.m8n8.x4.trans.shared.b16 {%0,%1,%2,%3}, [%4];"
                 : "=r"(r[0]), "=r"(r[1]), "=r"(r[2]), "=r"(r[3]) : "r"(addr));
}
__device__ __forceinline__ void mma16816(float* c, const uint32_t* a,
                                         uint32_t b0, uint32_t b1) {
    asm volatile("mma.sync.aligned.m16n8k16.row.col.f32.bf16.bf16.f32 "
                 "{%0,%1,%2,%3}, {%4,%5,%6,%7}, {%8,%9}, {%0,%1,%2,%3};"
                 : "+f"(c[0]), "+f"(c[1]), "+f"(c[2]), "+f"(c[3])
                 : "r"(a[0]), "r"(a[1]), "r"(a[2]), "r"(a[3]), "r"(b0), "r"(b1));
}

// ---------------- small kernels ----------------
__global__ void k_init() {
    int idx = blockIdx.x * blockDim.x + threadIdx.x;
    if (idx < CLS) g_norm2[idx] = 0.0f;
    if (idx == 0) g_inter_sum = 0.0f;
}

// partial column norms: block (x: 256 j's, y: 64 i's) -> atomic add
__global__ void k_colnorm(const float* __restrict__ W) {
    int j = blockIdx.x * blockDim.x + threadIdx.x;
    if (j >= CLS) return;
    int i0 = blockIdx.y * 64;
    float s = 0.0f;
#pragma unroll 8
    for (int i = 0; i < 64; i++) {
        float v = W[(size_t)(i0 + i) * CLS + j];
        s += v * v;
    }
    atomicAdd(&g_norm2[j], s);
}

// fully parallel normalize + bf16 hi/lo split: block.y = i row, 8 j's per thread
__global__ void k_split(const float* __restrict__ W) {
    int i = blockIdx.y;
    int j0 = blockIdx.x * 2048 + threadIdx.x * 8;
    if (j0 >= CLS) return;
    size_t base = (size_t)i * CLS + j0;
    float4 v0 = *(const float4*)(W + base);
    float4 v1 = *(const float4*)(W + base + 4);
    float f[8] = {v0.x, v0.y, v0.z, v0.w, v1.x, v1.y, v1.z, v1.w};
    alignas(16) __nv_bfloat16 hb[8];
    alignas(16) __nv_bfloat16 lb[8];
#pragma unroll
    for (int q = 0; q < 8; q++) {
        float v = f[q] * rsqrtf(g_norm2[j0 + q]);
        __nv_bfloat16 h = __float2bfloat16(v);
        hb[q] = h;
        lb[q] = __float2bfloat16(v - __bfloat162float(h));
    }
    *(uint4*)(g_Bhi + base) = *(const uint4*)hb;
    *(uint4*)(g_Blo + base) = *(const uint4*)lb;
}

// 512 blocks: b<BB: emb split + xlen; else gather normalized target column
__global__ void k_prep(const float* __restrict__ emb,
                       const int* __restrict__ y) {
    int b = blockIdx.x;
    int tid = threadIdx.x;   // 128
    if (b < BB) {
        float s = 0.0f;
        for (int k = tid; k < EMB; k += 128) {
            float v = emb[b * EMB + k];
            s += v * v;
            __nv_bfloat16 h = __float2bfloat16(v);
            g_Ahi[b * EMB + k] = h;
            g_Alo[b * EMB + k] = __float2bfloat16(v - __bfloat162float(h));
        }
        __shared__ float sm[128];
        sm[tid] = s;
        __syncthreads();
        for (int o = 64; o > 0; o >>= 1) {
            if (tid < o) sm[tid] += sm[tid + o];
            __syncthreads();
        }
        if (tid == 0) g_xlen[b] = sqrtf(sm[0]);
    } else {
        int t = y[b - BB];
        for (int k = tid; k < EMB; k += 128) {
            g_Ahi[b * EMB + k] = g_Bhi[(size_t)k * CLS + t];
            g_Alo[b * EMB + k] = g_Blo[(size_t)k * CLS + t];
        }
    }
}

// ---------------- bf16 mma.sync fused GEMM (512 threads, 16 warps, 32x32 warp tile) ----------------
__global__ __launch_bounds__(512, 1) void k_gemm(const int* __restrict__ y,
                                                 float* __restrict__ logits) {
    extern __shared__ __align__(16) char dsm[];
    uint32_t sb = s2u(dsm);

    int tid  = threadIdx.x;
    int wid  = tid >> 5, lane = tid & 31;
    int wm   = wid & 3;           // M quarter (32 rows)
    int wn   = wid >> 2;          // N quarter (32 cols)
    int bn   = blockIdx.x, bm = blockIdx.y;
    int rowBase = bm * MT, colBase = bn * NT;

    float acc[2][4][4];
#pragma unroll
    for (int mi = 0; mi < 2; mi++)
#pragma unroll
        for (int ni = 0; ni < 4; ni++)
#pragma unroll
            for (int k = 0; k < 4; k++) acc[mi][ni][k] = 0.0f;

    // ---- async tile loader (512 threads, one 16B chunk each per array)
    auto load_tiles = [&](int kc, int buf) {
        uint32_t base = sb + buf * SBUF;
        {
            int r = tid >> 2, c8 = tid & 3;       // A: 128 rows x 4 chunks
            uint32_t soff = (uint32_t)(r * 64 + ((c8 ^ ((r >> 1) & 3)) << 4));
            size_t go = (size_t)(rowBase + r) * EMB + kc + c8 * 8;
            cp_async16(base + soff,        g_Ahi + go, 16);
            cp_async16(base + 8192 + soff, g_Alo + go, 16);
        }
        {
            int r = tid >> 4, c16 = tid & 15;     // B: 32 rows x 16 chunks
            uint32_t soff = (uint32_t)(r * 256 + ((c16 ^ (r & 7)) << 4));
            int col = colBase + c16 * 8;
            int ok = (col < CLS) ? 16 : 0;        // CLS%8==0 -> full chunk valid
            size_t go = (size_t)(kc + r) * CLS + (ok ? col : colBase);
            cp_async16(base + 16384 + soff, g_Bhi + go, ok);
            cp_async16(base + 24576 + soff, g_Blo + go, ok);
        }
    };

    load_tiles(0, 0);
    CP_COMMIT();

    int ln15 = lane & 15, half = lane >> 4;

    for (int ch = 0; ch < NCH; ch++) {
        if (ch + 1 < NCH) { load_tiles((ch + 1) * KC, (ch + 1) & 1); CP_COMMIT(); }
        if (ch + 1 < NCH) { CP_WAIT(1); } else { CP_WAIT(0); }
        __syncthreads();

        uint32_t base = sb + (ch & 1) * SBUF;
#pragma unroll
        for (int ks = 0; ks < 2; ks++) {
            uint32_t ah[2][4], al[2][4], bh[2][4], bl[2][4];
#pragma unroll
            for (int mi = 0; mi < 2; mi++) {
                int r = wm * 32 + mi * 16 + ln15;
                int c8 = ks * 2 + half;
                uint32_t off = (uint32_t)(r * 64 + ((c8 ^ ((r >> 1) & 3)) << 4));
                ldm_x4(ah[mi], base + off);
                ldm_x4(al[mi], base + 8192 + off);
            }
#pragma unroll
            for (int nb = 0; nb < 2; nb++) {
                int r = ks * 16 + ln15;
                int c16 = wn * 4 + nb * 2 + half;
                uint32_t off = (uint32_t)(r * 256 + ((c16 ^ (r & 7)) << 4));
                ldm_x4_t(bh[nb], base + 16384 + off);
                ldm_x4_t(bl[nb], base + 24576 + off);
            }
            // product-outer: 8 independent acc chains per product group
#pragma unroll
            for (int mi = 0; mi < 2; mi++)
#pragma unroll
                for (int ni = 0; ni < 4; ni++)
                    mma16816(acc[mi][ni], ah[mi],
                             bh[ni >> 1][(ni & 1) * 2], bh[ni >> 1][(ni & 1) * 2 + 1]);
#pragma unroll
            for (int mi = 0; mi < 2; mi++)
#pragma unroll
                for (int ni = 0; ni < 4; ni++)
                    mma16816(acc[mi][ni], al[mi],
                             bh[ni >> 1][(ni & 1) * 2], bh[ni >> 1][(ni & 1) * 2 + 1]);
#pragma unroll
            for (int mi = 0; mi < 2; mi++)
#pragma unroll
                for (int ni = 0; ni < 4; ni++)
                    mma16816(acc[mi][ni], ah[mi],
                             bl[ni >> 1][(ni & 1) * 2], bl[ni >> 1][(ni & 1) * 2 + 1]);
        }
        __syncthreads();
    }

    // ---------------- epilogue ----------------
    if (bm < 2) {
        float* epi = (float*)dsm;   // [128][129]
#pragma unroll
        for (int mi = 0; mi < 2; mi++)
#pragma unroll
            for (int ni = 0; ni < 4; ni++)
#pragma unroll
                for (int k = 0; k < 4; k++) {
                    int row = wm * 32 + mi * 16 + (k >> 1) * 8 + (lane >> 2);
                    int col = wn * 32 + ni * 8 + (lane & 3) * 2 + (k & 1);
                    epi[row * 129 + col] = acc[mi][ni][k];
                }
        __syncthreads();
        int r0 = tid >> 7, c0 = tid & 127;   // r0 0..3
        int j = colBase + c0;
        if (j < CLS) {
#pragma unroll 8
            for (int rr = 0; rr < 32; rr++) {
                int mm = rr * 4 + r0;
                int b = rowBase + mm;
                float xl = g_xlen[b];
                float v = epi[mm * 129 + c0];
                float cv = fminf(fmaxf(v / xl, -1.0f), 1.0f);
                logits[(size_t)b * CLS + j] = cv * xl;
            }
        }
    } else {
        float il = 0.0f;
#pragma unroll
        for (int mi = 0; mi < 2; mi++) {
#pragma unroll
            for (int k2 = 0; k2 < 2; k2++) {
                int row = wm * 32 + mi * 16 + k2 * 8 + (lane >> 2);
                int b = rowBase + row - BB;
                int t = y[b];
#pragma unroll
                for (int ni = 0; ni < 4; ni++)
#pragma unroll
                    for (int p = 0; p < 2; p++) {
                        int j = colBase + wn * 32 + ni * 8 + (lane & 3) * 2 + p;
                        if (j < CLS && j != t) {
                            float c = acc[mi][ni][k2 * 2 + p];
                            float d2 = fmaxf(2.0f - 2.0f * c, 0.0f);
                            il += 1.0f / d2;
                        }
                    }
            }
        }
#pragma unroll
        for (int o = 16; o > 0; o >>= 1)
            il += __shfl_down_sync(0xffffffffu, il, o);
        if (lane == 0) atomicAdd(&g_inter_sum, il);
    }
}

// ---------------- per-row: margin target, log-softmax, argmax ----------------
__global__ __launch_bounds__(256) void k_rows(const float* __restrict__ logits,
                                              const int* __restrict__ y) {
    int b = blockIdx.x;
    int tid = threadIdx.x;
    int tgt = y[b];
    float xl = g_xlen[b];
    const float* row = logits + (size_t)b * CLS;

    float cs_t = row[tgt];
    float ct = cs_t / xl;
    float c2 = ct * ct;
    float cosm = 8.0f * c2 * c2 - 8.0f * c2 + 1.0f;
    const float PI_F = 3.14159265f;
    float theta = acosf(ct);
    float kk = floorf(4.0f * theta / PI_F);
    float sign = 1.0f - 2.0f * fmodf(kk, 2.0f);
    float phi = sign * cosm - 2.0f * kk;
    const float LAMB = 1500.0f / 1.1f;
    const float FCO = 1.0f / (1.0f + LAMB);
    float out_t = cs_t + FCO * (phi * xl - cs_t);

    float mx = -3.0e38f, bv = -3.0e38f;
    int bi = CLS;
    for (int j = tid; j < CLS; j += 256) {
        float v = row[j];
        float ov = (j == tgt) ? out_t : v;
        mx = fmaxf(mx, ov);
        if (v > bv) { bv = v; bi = j; }
    }
    __shared__ float smx[256];
    __shared__ float sbv[256];
    __shared__ int   sbi[256];
    smx[tid] = mx; sbv[tid] = bv; sbi[tid] = bi;
    __syncthreads();
    for (int o = 128; o > 0; o >>= 1) {
        if (tid < o) {
            smx[tid] = fmaxf(smx[tid], smx[tid + o]);
            float v2 = sbv[tid + o]; int i2 = sbi[tid + o];
            if (v2 > sbv[tid] || (v2 == sbv[tid] && i2 < sbi[tid])) {
                sbv[tid] = v2; sbi[tid] = i2;
            }
        }
        __syncthreads();
    }
    float rmx = smx[0];
    int amax = sbi[0];
    __syncthreads();

    float se = 0.0f;
    for (int j = tid; j < CLS; j += 256) {
        float v = row[j];
        float ov = (j == tgt) ? out_t : v;
        se += expf(ov - rmx);
    }
    smx[tid] = se;
    __syncthreads();
    for (int o = 128; o > 0; o >>= 1) {
        if (tid < o) smx[tid] += smx[tid + o];
        __syncthreads();
    }
    if (tid == 0) {
        float lse = logf(smx[0]);
        g_row_ce[b] = -(out_t - rmx - lse);
        g_row_correct[b] = (amax == tgt) ? 1 : 0;
    }
}

__global__ __launch_bounds__(256) void k_final(float* __restrict__ out) {
    __shared__ float s[256];
    __shared__ int   c[256];
    int tid = threadIdx.x;
    s[tid] = g_row_ce[tid];
    c[tid] = g_row_correct[tid];
    __syncthreads();
    for (int o = 128; o > 0; o >>= 1) {
        if (tid < o) { s[tid] += s[tid + o]; c[tid] += c[tid + o]; }
        __syncthreads();
    }
    if (tid == 0) {
        float ce = s[0] / (float)BB;
        float inter = g_inter_sum / ((float)BB * (float)(CLS - 1));
        out[0] = ce + 0.01f * inter;
        out[1 + BB * CLS] = (float)c[0] / (float)BB;
        out[2 + BB * CLS] = inter;
    }
}

// ---------------- launch ----------------
extern "C" void kernel_launch(void* const* d_in, const int* in_sizes, int n_in,
                              void* d_out, int out_size) {
    const float* emb = (const float*)d_in[0];
    const int*   y   = (const int*)d_in[1];
    const float* W   = (const float*)d_in[2];
    float* out = (float*)d_out;
    float* logits = out + 1;

    const int DSM = 68 * 1024;   // 2x32KB pipeline buffers; 128x129 f32 epi tile fits too
    cudaFuncSetAttribute(k_gemm, cudaFuncAttributeMaxDynamicSharedMemorySize, DSM);

    k_init<<<(CLS + 255) / 256, 256>>>();
    dim3 gcn((CLS + 255) / 256, EMB / 64);           // 79 x 8
    k_colnorm<<<gcn, 256>>>(W);
    dim3 gsp((CLS + 2047) / 2048, EMB);              // 10 x 512
    k_split<<<gsp, 256>>>(W);
    k_prep<<<2 * BB, 128>>>(emb, y);
    dim3 grid((CLS + NT - 1) / NT, (2 * BB) / MT);   // 157 x 4
    k_gemm<<<grid, 512, DSM>>>(y, logits);
    k_rows<<<BB, 256>>>(logits, y);
    k_final<<<1, 256>>>(out);
}